// round 1
// baseline (speedup 1.0000x reference)
#include <cuda_runtime.h>
#include <math.h>

// Problem constants
#define PATCH   32
#define HP      256
#define WP      256
#define NPATCH  (HP * WP)     // 65536
#define IMG_W   8192

// ln(0.04 * sqrt(2*pi))
#define LOG_NORM_CONST (-2.2999372199f)

// Scratch for patch means (allocation-free per harness rules)
__device__ float g_means[NPATCH];

// Kernel 1: one CTA per 32x32 patch. 256 threads, each loads one float4
// (8 threads x 16B = 128B = one patch row). Tree-reduce to patch mean.
__global__ void patch_mean_kernel(const float* __restrict__ x) {
    const int p   = blockIdx.x;          // patch index, row-major [hp, wp]
    const int ph  = p >> 8;              // / 256
    const int pw  = p & 255;             // % 256
    const int tid = threadIdx.x;
    const int row = tid >> 3;            // 0..31 row within patch
    const int q   = tid & 7;             // 0..7 float4 within row

    const size_t base = (size_t)(ph * PATCH + row) * IMG_W + (size_t)pw * PATCH;
    const float4 v = *((const float4*)(x + base) + q);

    float s = (v.x + v.y) + (v.z + v.w);

    // warp reduce
    #pragma unroll
    for (int o = 16; o > 0; o >>= 1)
        s += __shfl_xor_sync(0xffffffffu, s, o);

    __shared__ float ws[8];
    if ((tid & 31) == 0) ws[tid >> 5] = s;
    __syncthreads();

    if (tid < 8) {
        float t = ws[tid];
        #pragma unroll
        for (int o = 4; o > 0; o >>= 1)
            t += __shfl_xor_sync(0xffu, t, o);
        if (tid == 0)
            g_means[p] = t * (1.0f / (PATCH * PATCH));
    }
}

// Kernel 2: single CTA masked reduction over 65536 patch means -> scalar loss.
__global__ void loss_kernel(const float* __restrict__ tmask, float* __restrict__ out) {
    const int tid = threadIdx.x;

    double pos_s = 0.0, neg_s = 0.0;
    float  pos_c = 0.0f, neg_c = 0.0f;

    for (int i = tid; i < NPATCH; i += 1024) {
        const float m = g_means[i];
        if (tmask[i] >= 0.5f) {
            const float z = (m - 0.34f) * 25.0f;           // (m - mu) / std
            const float logpdf = -0.5f * z * z - LOG_NORM_CONST;
            const float pt = -logf(expf(logpdf) + 1e-6f);
            pos_s += (double)pt;
            pos_c += 1.0f;
        } else {
            neg_s += (double)m * (double)m;
            neg_c += 1.0f;
        }
    }

    // warp reduce 4 accumulators
    #pragma unroll
    for (int o = 16; o > 0; o >>= 1) {
        pos_s += __shfl_xor_sync(0xffffffffu, pos_s, o);
        neg_s += __shfl_xor_sync(0xffffffffu, neg_s, o);
        pos_c += __shfl_xor_sync(0xffffffffu, pos_c, o);
        neg_c += __shfl_xor_sync(0xffffffffu, neg_c, o);
    }

    __shared__ double s_ps[32], s_ns[32];
    __shared__ float  s_pc[32], s_nc[32];
    const int wid = tid >> 5;
    if ((tid & 31) == 0) {
        s_ps[wid] = pos_s; s_ns[wid] = neg_s;
        s_pc[wid] = pos_c; s_nc[wid] = neg_c;
    }
    __syncthreads();

    if (tid < 32) {
        pos_s = s_ps[tid]; neg_s = s_ns[tid];
        pos_c = s_pc[tid]; neg_c = s_nc[tid];
        #pragma unroll
        for (int o = 16; o > 0; o >>= 1) {
            pos_s += __shfl_xor_sync(0xffffffffu, pos_s, o);
            neg_s += __shfl_xor_sync(0xffffffffu, neg_s, o);
            pos_c += __shfl_xor_sync(0xffffffffu, pos_c, o);
            neg_c += __shfl_xor_sync(0xffffffffu, neg_c, o);
        }
        if (tid == 0) {
            const double loss = pos_s / (double)pos_c + neg_s / (double)neg_c;
            out[0] = (float)loss;
        }
    }
}

extern "C" void kernel_launch(void* const* d_in, const int* in_sizes, int n_in,
                              void* d_out, int out_size) {
    const float* unet  = (const float*)d_in[0];   // [1,1,8192,8192] fp32
    const float* tmask = (const float*)d_in[1];   // [1,256,256] fp32
    float* out = (float*)d_out;

    patch_mean_kernel<<<NPATCH, 256>>>(unet);
    loss_kernel<<<1, 1024>>>(tmask, out);
}

// round 2
// speedup vs baseline: 2.3276x; 2.3276x over previous
#include <cuda_runtime.h>
#include <math.h>

#define PATCH   32
#define HP      256
#define WP      256
#define NPATCH  (HP * WP)     // 65536
#define IMG_W   8192
#define NGROUP  (NPATCH / 4)  // 16384 CTAs, 4 patches each

// ln(0.04 * sqrt(2*pi)) = -2.2999372...
#define LOG_NORM_CONST (-2.2999372199f)

// Per-patch (pos_term, neg_term), written by kernel 1.
__device__ float2 g_terms[NPATCH];

// Kernel 1: one CTA per group of 4 horizontally adjacent patches.
// 256 threads; thread (row = tid>>3, q = tid&7) loads 4 independent float4s
// (one per patch) from the same image row -> MLP 4, full 128B coalescing.
__global__ void patch_mean_kernel(const float* __restrict__ x) {
    const int g   = blockIdx.x;          // group index
    const int ph  = g >> 6;              // patch row (256/4 = 64 groups per row)
    const int pg  = g & 63;              // group col
    const int tid = threadIdx.x;
    const int row = tid >> 3;            // 0..31
    const int q   = tid & 7;             // 0..7

    const size_t base = (size_t)(ph * PATCH + row) * IMG_W + (size_t)pg * 128;
    const float4* p4 = (const float4*)(x + base);

    float s[4];
    #pragma unroll
    for (int k = 0; k < 4; k++) {
        const float4 v = p4[k * 8 + q];
        s[k] = (v.x + v.y) + (v.z + v.w);
    }

    // Full-warp xor reduce each of the 4 partials (warp covers 4 rows x 8 q
    // of every patch, so a full 32-lane reduce gives 4-row x 32-col sums).
    #pragma unroll
    for (int o = 16; o > 0; o >>= 1) {
        #pragma unroll
        for (int k = 0; k < 4; k++)
            s[k] += __shfl_xor_sync(0xffffffffu, s[k], o);
    }

    __shared__ float sm[8][4];
    const int w = tid >> 5;
    if ((tid & 31) == 0) {
        #pragma unroll
        for (int k = 0; k < 4; k++) sm[w][k] = s[k];
    }
    __syncthreads();

    // 32 threads: lane = warp*4 + k layout; reduce across the 8 warps.
    if (tid < 32) {
        float v = sm[tid >> 2][tid & 3];
        v += __shfl_xor_sync(0xffffffffu, v, 4);
        v += __shfl_xor_sync(0xffffffffu, v, 8);
        v += __shfl_xor_sync(0xffffffffu, v, 16);
        if (tid < 4) {
            const float mean = v * (1.0f / (PATCH * PATCH));
            // positive branch term (mask applied later)
            const float z = (mean - 0.34f) * 25.0f;
            const float logpdf = -0.5f * z * z - LOG_NORM_CONST;
            const float pos_t = -logf(expf(logpdf) + 1e-6f);
            const float neg_t = mean * mean;
            g_terms[ph * WP + pg * 4 + tid] = make_float2(pos_t, neg_t);
        }
    }
}

// Kernel 2: single-CTA pure reduction (no exp/log on the critical path).
__global__ void loss_kernel(const float* __restrict__ tmask, float* __restrict__ out) {
    const int tid = threadIdx.x;

    float pos_s = 0.0f, neg_s = 0.0f, pos_c = 0.0f;

    #pragma unroll 4
    for (int i = tid; i < NPATCH; i += 1024) {
        const float2 t = g_terms[i];
        const float  m = tmask[i];
        if (m >= 0.5f) { pos_s += t.x; pos_c += 1.0f; }
        else           { neg_s += t.y; }
    }

    #pragma unroll
    for (int o = 16; o > 0; o >>= 1) {
        pos_s += __shfl_xor_sync(0xffffffffu, pos_s, o);
        neg_s += __shfl_xor_sync(0xffffffffu, neg_s, o);
        pos_c += __shfl_xor_sync(0xffffffffu, pos_c, o);
    }

    __shared__ float s_ps[32], s_ns[32], s_pc[32];
    const int wid = tid >> 5;
    if ((tid & 31) == 0) { s_ps[wid] = pos_s; s_ns[wid] = neg_s; s_pc[wid] = pos_c; }
    __syncthreads();

    if (tid < 32) {
        pos_s = s_ps[tid]; neg_s = s_ns[tid]; pos_c = s_pc[tid];
        #pragma unroll
        for (int o = 16; o > 0; o >>= 1) {
            pos_s += __shfl_xor_sync(0xffffffffu, pos_s, o);
            neg_s += __shfl_xor_sync(0xffffffffu, neg_s, o);
            pos_c += __shfl_xor_sync(0xffffffffu, pos_c, o);
        }
        if (tid == 0) {
            const float neg_c = (float)NPATCH - pos_c;
            out[0] = pos_s / pos_c + neg_s / neg_c;
        }
    }
}

extern "C" void kernel_launch(void* const* d_in, const int* in_sizes, int n_in,
                              void* d_out, int out_size) {
    const float* unet  = (const float*)d_in[0];   // [1,1,8192,8192] fp32
    const float* tmask = (const float*)d_in[1];   // [1,256,256] fp32
    float* out = (float*)d_out;

    patch_mean_kernel<<<NGROUP, 256>>>(unet);
    loss_kernel<<<1, 1024>>>(tmask, out);
}

// round 3
// speedup vs baseline: 3.0107x; 1.2934x over previous
#include <cuda_runtime.h>
#include <math.h>

#define PATCH   32
#define HP      256
#define WP      256
#define NPATCH  (HP * WP)     // 65536
#define IMG_W   8192
#define NGROUP  (NPATCH / 4)  // 16384 CTAs, 4 patches each

// ln(0.04 * sqrt(2*pi)) = -2.2999372...
#define LOG_NORM_CONST (-2.2999372199f)

// Per-CTA partials: (pos_sum, neg_sum, pos_count, unused)
__device__ float4 g_part[NGROUP];

// Kernel 1: one CTA per group of 4 horizontally adjacent patches.
// 256 threads; thread (row = tid>>3, q = tid&7) loads 4 independent float4s
// (one per patch) from the same image row -> MLP 4, full 128B coalescing.
// Tail: compute means, pos/neg terms, apply mask, emit ONE float4 partial.
__global__ void patch_mean_kernel(const float* __restrict__ x,
                                  const float* __restrict__ tmask) {
    const int g   = blockIdx.x;          // group index
    const int ph  = g >> 6;              // patch row (64 groups per row)
    const int pg  = g & 63;              // group col
    const int tid = threadIdx.x;
    const int row = tid >> 3;            // 0..31
    const int q   = tid & 7;             // 0..7

    const size_t base = (size_t)(ph * PATCH + row) * IMG_W + (size_t)pg * 128;
    const float4* p4 = (const float4*)(x + base);

    float s[4];
    #pragma unroll
    for (int k = 0; k < 4; k++) {
        const float4 v = p4[k * 8 + q];
        s[k] = (v.x + v.y) + (v.z + v.w);
    }

    // Full-warp xor reduce each of the 4 partials.
    #pragma unroll
    for (int o = 16; o > 0; o >>= 1) {
        #pragma unroll
        for (int k = 0; k < 4; k++)
            s[k] += __shfl_xor_sync(0xffffffffu, s[k], o);
    }

    __shared__ float sm[8][4];
    const int w = tid >> 5;
    if ((tid & 31) == 0) {
        #pragma unroll
        for (int k = 0; k < 4; k++) sm[w][k] = s[k];
    }
    __syncthreads();

    if (tid < 32) {
        // lane = warp*4 + k layout; reduce across the 8 warps.
        float v = sm[tid >> 2][tid & 3];
        v += __shfl_xor_sync(0xffffffffu, v, 4);
        v += __shfl_xor_sync(0xffffffffu, v, 8);
        v += __shfl_xor_sync(0xffffffffu, v, 16);

        float ps = 0.0f, ns = 0.0f, pc = 0.0f;
        if (tid < 4) {
            const float mean = v * (1.0f / (PATCH * PATCH));
            const float z = (mean - 0.34f) * 25.0f;
            const float logpdf = -0.5f * z * z - LOG_NORM_CONST;
            const float pos_t = -logf(expf(logpdf) + 1e-6f);
            const float neg_t = mean * mean;
            const float mk = (tmask[ph * WP + pg * 4 + tid] >= 0.5f) ? 1.0f : 0.0f;
            ps = pos_t * mk;
            ns = neg_t * (1.0f - mk);
            pc = mk;
        }
        // reduce the 4 per-patch contributions (lanes 0..3 hold data; all 32 active)
        #pragma unroll
        for (int o = 2; o > 0; o >>= 1) {
            ps += __shfl_xor_sync(0xffffffffu, ps, o);
            ns += __shfl_xor_sync(0xffffffffu, ns, o);
            pc += __shfl_xor_sync(0xffffffffu, pc, o);
        }
        if (tid == 0)
            g_part[g] = make_float4(ps, ns, pc, 0.0f);
    }
}

// Kernel 2: single CTA reduces 16384 float4 partials (256 KB, L2-resident).
__global__ void loss_kernel(float* __restrict__ out) {
    const int tid = threadIdx.x;

    float ps = 0.0f, ns = 0.0f, pc = 0.0f;

    #pragma unroll
    for (int i = tid; i < NGROUP; i += 1024) {   // 16 independent float4 loads
        const float4 p = g_part[i];
        ps += p.x; ns += p.y; pc += p.z;
    }

    #pragma unroll
    for (int o = 16; o > 0; o >>= 1) {
        ps += __shfl_xor_sync(0xffffffffu, ps, o);
        ns += __shfl_xor_sync(0xffffffffu, ns, o);
        pc += __shfl_xor_sync(0xffffffffu, pc, o);
    }

    __shared__ float s_ps[32], s_ns[32], s_pc[32];
    const int wid = tid >> 5;
    if ((tid & 31) == 0) { s_ps[wid] = ps; s_ns[wid] = ns; s_pc[wid] = pc; }
    __syncthreads();

    if (tid < 32) {
        ps = s_ps[tid]; ns = s_ns[tid]; pc = s_pc[tid];
        #pragma unroll
        for (int o = 16; o > 0; o >>= 1) {
            ps += __shfl_xor_sync(0xffffffffu, ps, o);
            ns += __shfl_xor_sync(0xffffffffu, ns, o);
            pc += __shfl_xor_sync(0xffffffffu, pc, o);
        }
        if (tid == 0) {
            const float nc = (float)NPATCH - pc;
            out[0] = ps / pc + ns / nc;
        }
    }
}

extern "C" void kernel_launch(void* const* d_in, const int* in_sizes, int n_in,
                              void* d_out, int out_size) {
    const float* unet  = (const float*)d_in[0];   // [1,1,8192,8192] fp32
    const float* tmask = (const float*)d_in[1];   // [1,256,256] fp32
    float* out = (float*)d_out;

    patch_mean_kernel<<<NGROUP, 256>>>(unet, tmask);
    loss_kernel<<<1, 1024>>>(out);
}

// round 4
// speedup vs baseline: 3.1453x; 1.0447x over previous
#include <cuda_runtime.h>
#include <math.h>

#define PATCH    32
#define HP       256
#define WP       256
#define NPATCH   (HP * WP)        // 65536
#define IMG_W    8192
#define IMG_W4   (IMG_W / 4)      // 2048 float4 per row
#define PPB      64               // patches per CTA (8 warps x 8 iters)
#define NGRID1   (NPATCH / PPB)   // 1024 CTAs

// ln(0.04 * sqrt(2*pi)) = -2.2999372...
#define LOG_NORM_CONST (-2.2999372199f)

// Per-CTA partials: (pos_sum, neg_sum, pos_count, unused)
__device__ float4 g_part[NGRID1];

// Kernel 1: warp-per-patch. Each warp reduces one 32x32 patch per iteration
// (8 independent float4 loads per lane -> MLP 8), 8 iterations, no barriers
// in the loop. CTA covers 64 contiguous patches; tail computes 64 parallel
// pos/neg terms and emits ONE float4 partial.
__global__ void __launch_bounds__(256, 8)
patch_kernel(const float* __restrict__ x, const float* __restrict__ tmask) {
    const int tid = threadIdx.x;
    const int w   = tid >> 5;            // warp 0..7
    const int l   = tid & 31;            // lane
    const int p_base = blockIdx.x * PPB; // first patch of this CTA

    __shared__ float means[PPB];

    const int lrow = l >> 3;             // 0..3 base row
    const int lq   = l & 7;              // float4 within 128B row segment

    #pragma unroll
    for (int t = 0; t < 8; t++) {
        const int p  = p_base + t * 8 + w;
        const int ph = p >> 8;
        const int pw = p & 255;
        const float4* p4 = (const float4*)x
                         + (size_t)(ph * PATCH) * IMG_W4 + (size_t)pw * 8;

        float s = 0.0f;
        #pragma unroll
        for (int k = 0; k < 8; k++) {    // 8 independent loads in flight
            const float4 v = __ldcs(&p4[(size_t)(lrow + 4 * k) * IMG_W4 + lq]);
            s += (v.x + v.y) + (v.z + v.w);
        }

        #pragma unroll
        for (int o = 16; o > 0; o >>= 1)
            s += __shfl_xor_sync(0xffffffffu, s, o);

        if (l == 0) means[t * 8 + w] = s * (1.0f / (PATCH * PATCH));
    }
    __syncthreads();

    // Tail: 64 parallel term computations, then block reduce.
    float ps = 0.0f, ns = 0.0f, pc = 0.0f;
    if (tid < PPB) {
        const float mean = means[tid];
        const float z = (mean - 0.34f) * 25.0f;
        const float logpdf = -0.5f * z * z - LOG_NORM_CONST;
        const float pos_t = -logf(expf(logpdf) + 1e-6f);
        const float neg_t = mean * mean;
        const float mk = (tmask[p_base + tid] >= 0.5f) ? 1.0f : 0.0f;
        ps = pos_t * mk;
        ns = neg_t * (1.0f - mk);
        pc = mk;
    }

    // warps 0 and 1 hold data; reduce within each, combine via smem.
    if (tid < 64) {
        #pragma unroll
        for (int o = 16; o > 0; o >>= 1) {
            ps += __shfl_xor_sync(0xffffffffu, ps, o);
            ns += __shfl_xor_sync(0xffffffffu, ns, o);
            pc += __shfl_xor_sync(0xffffffffu, pc, o);
        }
    }
    __shared__ float3 pr[2];
    if (tid == 0 || tid == 32) pr[tid >> 5] = make_float3(ps, ns, pc);
    __syncthreads();
    if (tid == 0) {
        const float3 a = pr[0], b = pr[1];
        g_part[blockIdx.x] = make_float4(a.x + b.x, a.y + b.y, a.z + b.z, 0.0f);
    }
}

// Kernel 2: single CTA reduces 1024 float4 partials (16 KB, L2-resident).
__global__ void loss_kernel(float* __restrict__ out) {
    const int tid = threadIdx.x;

    const float4 p = g_part[tid];
    float ps = p.x, ns = p.y, pc = p.z;

    #pragma unroll
    for (int o = 16; o > 0; o >>= 1) {
        ps += __shfl_xor_sync(0xffffffffu, ps, o);
        ns += __shfl_xor_sync(0xffffffffu, ns, o);
        pc += __shfl_xor_sync(0xffffffffu, pc, o);
    }

    __shared__ float s_ps[32], s_ns[32], s_pc[32];
    const int wid = tid >> 5;
    if ((tid & 31) == 0) { s_ps[wid] = ps; s_ns[wid] = ns; s_pc[wid] = pc; }
    __syncthreads();

    if (tid < 32) {
        ps = s_ps[tid]; ns = s_ns[tid]; pc = s_pc[tid];
        #pragma unroll
        for (int o = 16; o > 0; o >>= 1) {
            ps += __shfl_xor_sync(0xffffffffu, ps, o);
            ns += __shfl_xor_sync(0xffffffffu, ns, o);
            pc += __shfl_xor_sync(0xffffffffu, pc, o);
        }
        if (tid == 0) {
            const float nc = (float)NPATCH - pc;
            out[0] = ps / pc + ns / nc;
        }
    }
}

extern "C" void kernel_launch(void* const* d_in, const int* in_sizes, int n_in,
                              void* d_out, int out_size) {
    const float* unet  = (const float*)d_in[0];   // [1,1,8192,8192] fp32
    const float* tmask = (const float*)d_in[1];   // [1,256,256] fp32
    float* out = (float*)d_out;

    patch_kernel<<<NGRID1, 256>>>(unet, tmask);
    loss_kernel<<<1, 1024>>>(out);
}

// round 5
// speedup vs baseline: 3.3118x; 1.0529x over previous
#include <cuda_runtime.h>
#include <math.h>

#define PATCH    32
#define HP       256
#define WP       256
#define NPATCH   (HP * WP)        // 65536
#define IMG_W    8192
#define IMG_W4   (IMG_W / 4)      // 2048 float4 per row
#define PPB      64               // patches per CTA (8 warps x 8 iters)
#define NGRID1   (NPATCH / PPB)   // 1024 CTAs

// ln(0.04 * sqrt(2*pi)) = -2.2999372...
#define LOG_NORM_CONST (-2.2999372199f)

// Per-CTA partials: (pos_sum, neg_sum, pos_count, unused)
__device__ float4 g_part[NGRID1];
__device__ unsigned int g_count;   // zero-initialized; reset by last CTA

// Fused kernel: warp-per-patch streaming reduce + last-CTA finish.
__global__ void __launch_bounds__(256, 8)
fused_kernel(const float* __restrict__ x, const float* __restrict__ tmask,
             float* __restrict__ out) {
    const int tid = threadIdx.x;
    const int w   = tid >> 5;            // warp 0..7
    const int l   = tid & 31;            // lane
    const int p_base = blockIdx.x * PPB; // first patch of this CTA

    __shared__ float means[PPB];

    const int lrow = l >> 3;             // 0..3 base row
    const int lq   = l & 7;              // float4 within 128B row segment

    #pragma unroll
    for (int t = 0; t < 8; t++) {
        const int p  = p_base + t * 8 + w;
        const int ph = p >> 8;
        const int pw = p & 255;
        const float4* p4 = (const float4*)x
                         + (size_t)(ph * PATCH) * IMG_W4 + (size_t)pw * 8;

        float s = 0.0f;
        #pragma unroll
        for (int k = 0; k < 8; k++) {    // 8 independent loads in flight
            const float4 v = __ldcs(&p4[(size_t)(lrow + 4 * k) * IMG_W4 + lq]);
            s += (v.x + v.y) + (v.z + v.w);
        }

        #pragma unroll
        for (int o = 16; o > 0; o >>= 1)
            s += __shfl_xor_sync(0xffffffffu, s, o);

        if (l == 0) means[t * 8 + w] = s * (1.0f / (PATCH * PATCH));
    }
    __syncthreads();

    // Tail: 64 parallel term computations, then block reduce.
    float ps = 0.0f, ns = 0.0f, pc = 0.0f;
    if (tid < PPB) {
        const float mean = means[tid];
        const float z = (mean - 0.34f) * 25.0f;
        const float logpdf = -0.5f * z * z - LOG_NORM_CONST;
        const float pos_t = -logf(expf(logpdf) + 1e-6f);
        const float neg_t = mean * mean;
        const float mk = (tmask[p_base + tid] >= 0.5f) ? 1.0f : 0.0f;
        ps = pos_t * mk;
        ns = neg_t * (1.0f - mk);
        pc = mk;
    }

    if (tid < 64) {
        #pragma unroll
        for (int o = 16; o > 0; o >>= 1) {
            ps += __shfl_xor_sync(0xffffffffu, ps, o);
            ns += __shfl_xor_sync(0xffffffffu, ns, o);
            pc += __shfl_xor_sync(0xffffffffu, pc, o);
        }
    }
    __shared__ float3 pr[2];
    if (tid == 0 || tid == 32) pr[tid >> 5] = make_float3(ps, ns, pc);
    __syncthreads();

    __shared__ bool s_last;
    if (tid == 0) {
        const float3 a = pr[0], b = pr[1];
        g_part[blockIdx.x] = make_float4(a.x + b.x, a.y + b.y, a.z + b.z, 0.0f);
        __threadfence();
        const unsigned int old = atomicAdd(&g_count, 1u);
        s_last = (old == NGRID1 - 1);
    }
    __syncthreads();

    if (!s_last) return;

    // ---- Last CTA: reduce all 1024 partials in fixed order (deterministic) ----
    float fps = 0.0f, fns = 0.0f, fpc = 0.0f;
    #pragma unroll
    for (int k = 0; k < NGRID1 / 256; k++) {      // 4 independent loads
        const float4 p = g_part[tid + k * 256];
        fps += p.x; fns += p.y; fpc += p.z;
    }

    #pragma unroll
    for (int o = 16; o > 0; o >>= 1) {
        fps += __shfl_xor_sync(0xffffffffu, fps, o);
        fns += __shfl_xor_sync(0xffffffffu, fns, o);
        fpc += __shfl_xor_sync(0xffffffffu, fpc, o);
    }

    __shared__ float f_ps[8], f_ns[8], f_pc[8];
    if (l == 0) { f_ps[w] = fps; f_ns[w] = fns; f_pc[w] = fpc; }
    __syncthreads();

    if (tid < 8) {
        fps = f_ps[tid]; fns = f_ns[tid]; fpc = f_pc[tid];
        #pragma unroll
        for (int o = 4; o > 0; o >>= 1) {
            fps += __shfl_xor_sync(0xffu, fps, o);
            fns += __shfl_xor_sync(0xffu, fns, o);
            fpc += __shfl_xor_sync(0xffu, fpc, o);
        }
        if (tid == 0) {
            const float fnc = (float)NPATCH - fpc;
            out[0] = fps / fpc + fns / fnc;
            g_count = 0;                  // reset for next graph replay
        }
    }
}

extern "C" void kernel_launch(void* const* d_in, const int* in_sizes, int n_in,
                              void* d_out, int out_size) {
    const float* unet  = (const float*)d_in[0];   // [1,1,8192,8192] fp32
    const float* tmask = (const float*)d_in[1];   // [1,256,256] fp32
    float* out = (float*)d_out;

    fused_kernel<<<NGRID1, 256>>>(unet, tmask, out);
}